// round 9
// baseline (speedup 1.0000x reference)
#include <cuda_runtime.h>
#include <cuda_fp16.h>
#include <cstdint>

#define NROWS  4096
#define DMODEL 512
#define DK     64
#define ND     (NROWS * DMODEL)
#define DD     (DMODEL * DMODEL)

// ---------------- scratch (device globals; allocation-free) -----------------
__device__ __half g_qkv[3][ND];         // fp16 Q/K/V projections
__device__ __half g_xh[3][ND];          // fp16 activations
__device__ __half g_wth[4][DD];         // weight^T fp16
__device__ __half g_yh[ND];             // attention output (fp16)
__device__ int    g_mflag[32];          // QKV m-block completion (target 24)
__device__ int    g_aflag[32];          // attention m-block completion (target 32)

// ---------------- PTX helpers ----------------
static __device__ __forceinline__ uint32_t s2u(const void* p) {
    uint32_t a;
    asm("{ .reg .u64 t; cvta.to.shared.u64 t, %1; cvt.u32.u64 %0, t; }" : "=r"(a) : "l"(p));
    return a;
}
static __device__ __forceinline__ void cp16(uint32_t s, const void* g) {
    asm volatile("cp.async.cg.shared.global [%0], [%1], 16;" :: "r"(s), "l"(g));
}
static __device__ __forceinline__ void ldsm4(uint32_t& r0, uint32_t& r1, uint32_t& r2,
                                             uint32_t& r3, uint32_t a) {
    asm volatile("ldmatrix.sync.aligned.m8n8.x4.shared.b16 {%0,%1,%2,%3}, [%4];"
                 : "=r"(r0), "=r"(r1), "=r"(r2), "=r"(r3) : "r"(a));
}
static __device__ __forceinline__ void mma_f16(float* c, const uint32_t* a, const uint32_t* b) {
    asm volatile(
        "mma.sync.aligned.m16n8k16.row.col.f32.f16.f16.f32 "
        "{%0,%1,%2,%3}, {%4,%5,%6,%7}, {%8,%9}, {%0,%1,%2,%3};"
        : "+f"(c[0]), "+f"(c[1]), "+f"(c[2]), "+f"(c[3])
        : "r"(a[0]), "r"(a[1]), "r"(a[2]), "r"(a[3]), "r"(b[0]), "r"(b[1]));
}
#define SWZ(x) ((x) ^ (((x) >> 3) & 0x70))

// ---------------- GEMM body: C[128x64 tile] = A @ B^T + bias ----------------
// fp16 in, fp32 accum. 256 threads (8 warps: 4m x 2n, warp tile 32x32),
// K=512 in 8 chunks of 64, 4-stage cp.async pipeline (24KB/stage).
#define KCHUNKS 8
#define STAGE_BYTES 24576
#define GSMEM_TOTAL (4 * STAGE_BYTES)

template <typename OutT>
static __device__ __forceinline__
void gemm_body(const __half* __restrict__ A, const __half* __restrict__ B,
               const float* __restrict__ bias, OutT* __restrict__ C,
               int m0, int n0, char* smem, int tid)
{
    const uint32_t sb = s2u(smem);
    const int wid = tid >> 5, lane = tid & 31;
    const int wm = wid & 3, wn = wid >> 2;

    const int a_row  = (wm << 5) + (lane & 15);
    const int a_kh   = lane >> 4;
    const int b_row0 = (wn << 5) + (((lane >> 4) & 1) << 3) + (lane & 7);
    const int b_kh   = (lane >> 3) & 1;

    float acc[2][4][4];
    #pragma unroll
    for (int i = 0; i < 2; i++)
        #pragma unroll
        for (int j = 0; j < 4; j++)
            #pragma unroll
            for (int r = 0; r < 4; r++) acc[i][j][r] = 0.f;

    auto load_stage = [&](int chunk, int st) {
        const uint32_t base = sb + st * STAGE_BYTES;
        const int k0 = chunk << 6;
        #pragma unroll
        for (int i = 0; i < 4; i++) {
            const int idx = (i << 8) + tid;
            const int row = idx >> 3, c = idx & 7;
            const uint32_t so = SWZ((row << 7) + (c << 4));
            const size_t aoff = (((size_t)(m0 + row) << 9) + k0 + (c << 3)) * 2;
            cp16(base + so, (const char*)A + aoff);
        }
        #pragma unroll
        for (int i = 0; i < 2; i++) {
            const int idx = (i << 8) + tid;
            const int row = idx >> 3, c = idx & 7;
            const uint32_t so = SWZ((row << 7) + (c << 4));
            const size_t boff = (((size_t)(n0 + row) << 9) + k0 + (c << 3)) * 2;
            cp16(base + 16384 + so, (const char*)B + boff);
        }
    };

    load_stage(0, 0);
    asm volatile("cp.async.commit_group;" ::: "memory");
    load_stage(1, 1);
    asm volatile("cp.async.commit_group;" ::: "memory");
    load_stage(2, 2);
    asm volatile("cp.async.commit_group;" ::: "memory");

    #pragma unroll
    for (int c = 0; c < KCHUNKS; c++) {
        const int pend = (7 - c) < 2 ? (7 - c) : 2;
        if (pend == 2)      asm volatile("cp.async.wait_group 2;" ::: "memory");
        else if (pend == 1) asm volatile("cp.async.wait_group 1;" ::: "memory");
        else                asm volatile("cp.async.wait_group 0;" ::: "memory");
        __syncthreads();

        if (c + 3 < KCHUNKS) {
            load_stage(c + 3, (c + 3) & 3);
            asm volatile("cp.async.commit_group;" ::: "memory");
        }

        const uint32_t stb = sb + (c & 3) * STAGE_BYTES;
        #pragma unroll
        for (int t = 0; t < 4; t++) {
            uint32_t ah[2][4], bh[4][2];
            #pragma unroll
            for (int mi = 0; mi < 2; mi++) {
                const int row = a_row + (mi << 4);
                const uint32_t so = SWZ((row << 7) + (((t << 1) + a_kh) << 4));
                ldsm4(ah[mi][0], ah[mi][1], ah[mi][2], ah[mi][3], stb + so);
            }
            #pragma unroll
            for (int pr = 0; pr < 2; pr++) {
                const int row = b_row0 + (pr << 4);
                const uint32_t so = SWZ((row << 7) + (((t << 1) + b_kh) << 4));
                ldsm4(bh[2 * pr][0], bh[2 * pr][1], bh[2 * pr + 1][0], bh[2 * pr + 1][1],
                      stb + 16384 + so);
            }
            #pragma unroll
            for (int mi = 0; mi < 2; mi++)
                #pragma unroll
                for (int ni = 0; ni < 4; ni++)
                    mma_f16(acc[mi][ni], ah[mi], bh[ni]);
        }
    }

    #pragma unroll
    for (int mi = 0; mi < 2; mi++) {
        const int row = m0 + (wm << 5) + (mi << 4) + (lane >> 2);
        #pragma unroll
        for (int ni = 0; ni < 4; ni++) {
            const int col = n0 + (wn << 5) + (ni << 3) + ((lane & 3) << 1);
            const float b0 = __ldg(bias + col), b1 = __ldg(bias + col + 1);
            if constexpr (sizeof(OutT) == 4) {
                float2 o0 = {acc[mi][ni][0] + b0, acc[mi][ni][1] + b1};
                float2 o1 = {acc[mi][ni][2] + b0, acc[mi][ni][3] + b1};
                *(float2*)((float*)C + (size_t)row * DMODEL + col)       = o0;
                *(float2*)((float*)C + (size_t)(row + 8) * DMODEL + col) = o1;
            } else {
                __half2 o0 = __floats2half2_rn(acc[mi][ni][0] + b0, acc[mi][ni][1] + b1);
                __half2 o1 = __floats2half2_rn(acc[mi][ni][2] + b0, acc[mi][ni][3] + b1);
                *(__half2*)((__half*)C + (size_t)row * DMODEL + col)       = o0;
                *(__half2*)((__half*)C + (size_t)(row + 8) * DMODEL + col) = o1;
            }
        }
    }
}

// ---------------- megakernel: QKV GEMM -> attention -> O GEMM ----------------
// bids [0,768): QKV. m = bid/24 (contiguous per m-block), rem: z = rem/8, n = rem%8.
// bids [768,1792): attention, 4 rows per CTA (r0 = 4*(bid-768)).
// bids [1792,2048): O GEMM. idx: m = idx/8, n = idx%8.
// Producers fence+atomicAdd per-m-block flags; consumers spin (tid 0) then barrier.
// Deadlock-free: HW dispatches CTAs in bid order, so all producers start before
// any consumer occupies a slot.
struct MegaArgs {
    const __half* xh;
    const __half* wth;
    const float*  bias[4];   // bq, bk, bv, bo
    __half*       qkv;
    const float*  xq;
    __half*       yh;
    float*        out;
};

__global__ __launch_bounds__(256, 2)
void mega(MegaArgs a)
{
    extern __shared__ char smem[];
    const int bid = blockIdx.x, tid = threadIdx.x;

    if (bid < 768) {
        // ---- QKV projection tile ----
        const int m = bid / 24, rem = bid % 24, z = rem >> 3, n = rem & 7;
        gemm_body<__half>(a.xh + (size_t)z * ND, a.wth + (size_t)z * DD, a.bias[z],
                          a.qkv + (size_t)z * ND, m << 7, n << 6, smem, tid);
        __threadfence();
        __syncthreads();
        if (tid == 0) atomicAdd(&g_mflag[m], 1);
    } else if (bid < 768 + 1024) {
        // ---- attention + residual, 4 rows ----
        const int r0 = (bid - 768) << 2;
        const int mblk = r0 >> 7;
        if (tid == 0) {
            while (atomicAdd(&g_mflag[mblk], 0) < 24) __nanosleep(128);
            __threadfence();
        }
        __syncthreads();

        __shared__ __half2 sk2[8][DK];
        __shared__ __half2 sv2[8][DK];
        const int warp = tid >> 5, lane = tid & 31;
        const __half* __restrict__ q = a.qkv;
        const __half* __restrict__ k = a.qkv + ND;
        const __half* __restrict__ v = a.qkv + 2 * (size_t)ND;
        const float SCL = 0.125f * 1.4426950408889634f;

        #pragma unroll
        for (int rr = 0; rr < 4; rr++) {
            const int base = (r0 + rr) * DMODEL + warp * DK;
            sk2[warp][lane]      = __half2half2(k[base + lane]);
            sk2[warp][lane + 32] = __half2half2(k[base + lane + 32]);
            sv2[warp][lane]      = __half2half2(v[base + lane]);
            sv2[warp][lane + 32] = __half2half2(v[base + lane + 32]);
            const __half2 a01 = __floats2half2_rn(__half2float(q[base + lane]) * SCL,
                                                  __half2float(q[base + lane + 32]) * SCL);
            __syncwarp();

            float num0 = 0.f, num1 = 0.f, den0 = 0.f, den1 = 0.f;
            #pragma unroll
            for (int jc = 0; jc < 4; jc++) {
                __half2 np = __float2half2_rn(0.f);
                __half2 dp = __float2half2_rn(0.f);
                #pragma unroll
                for (int j16 = 0; j16 < 16; j16++) {
                    const int j = (jc << 4) + j16;
                    const __half2 e = h2exp2(__hmul2(a01, sk2[warp][j]));
                    np = __hfma2(e, sv2[warp][j], np);
                    dp = __hadd2(dp, e);
                }
                const float2 nf = __half22float2(np);
                const float2 df = __half22float2(dp);
                num0 += nf.x; num1 += nf.y;
                den0 += df.x; den1 += df.y;
            }
            const float y0 = a.xq[base + lane]      - __fdividef(num0, den0);
            const float y1 = a.xq[base + lane + 32] - __fdividef(num1, den1);
            a.yh[base + lane]      = __float2half(y0);
            a.yh[base + lane + 32] = __float2half(y1);
            __syncwarp();   // smem rows are warp-private; warp sync suffices
        }
        __threadfence();
        __syncthreads();
        if (tid == 0) atomicAdd(&g_aflag[mblk], 1);
    } else {
        // ---- output projection tile ----
        const int idx = bid - (768 + 1024);
        const int m = idx >> 3, n = idx & 7;
        if (tid == 0) {
            while (atomicAdd(&g_aflag[m], 0) < 32) __nanosleep(128);
            __threadfence();
        }
        __syncthreads();
        gemm_body<float>(a.yh, a.wth + 3 * (size_t)DD, a.bias[3], a.out,
                         m << 7, n << 6, smem, tid);
    }
}

// ---------------- fused preprocessing (+ flag reset): one launch -------------
__global__ __launch_bounds__(256)
void preprocess(const float* __restrict__ w0, const float* __restrict__ w1,
                const float* __restrict__ w2, const float* __restrict__ w3,
                const float* __restrict__ x0, const float* __restrict__ x1,
                const float* __restrict__ x2,
                __half* __restrict__ Th, __half* __restrict__ H)
{
    const int bx = blockIdx.x, tid = threadIdx.x;
    if (bx == 0 && tid < 32) {   // reset flags for this graph replay
        g_mflag[tid] = 0;
        g_aflag[tid] = 0;
    }
    if (bx < 1024) {
        __shared__ float t[32][33];
        const int z = bx >> 8, b = bx & 255;
        const float* __restrict__ W = (z == 0) ? w0 : (z == 1) ? w1 : (z == 2) ? w2 : w3;
        __half* __restrict__ th = Th + (size_t)z * DD;
        const int bxe = (b & 15) * 32, bye = (b >> 4) * 32;
        const int tx = tid & 31, ty = tid >> 5;
        const int x = bxe + tx;
        #pragma unroll
        for (int j = 0; j < 32; j += 8)
            t[ty + j][tx] = W[(size_t)(bye + ty + j) * DMODEL + x];
        __syncthreads();
        const int ox = bye + tx;
        #pragma unroll
        for (int j = 0; j < 32; j += 8)
            th[(size_t)(bxe + ty + j) * DMODEL + ox] = __float2half(t[tx][ty + j]);
    } else {
        const int idx = bx - 1024;
        const int z = idx >> 11;
        const int blk = idx & 2047;
        const float* __restrict__ X = (z == 0) ? x0 : (z == 1) ? x1 : x2;
        const int i = (blk * 256 + tid) << 2;
        const float4 v = *(const float4*)(X + i);
        __half2 p0 = __floats2half2_rn(v.x, v.y);
        __half2 p1 = __floats2half2_rn(v.z, v.w);
        uint2 o = {*(uint32_t*)&p0, *(uint32_t*)&p1};
        *(uint2*)(H + (size_t)z * ND + i) = o;
    }
}

// ---------------- launch ------------------------------------------------------
extern "C" void kernel_launch(void* const* d_in, const int* in_sizes, int n_in,
                              void* d_out, int out_size)
{
    const float* x_q = (const float*)d_in[0];
    const float* x_k = (const float*)d_in[1];
    const float* x_v = (const float*)d_in[2];
    const float* Wq = (const float*)d_in[3];
    const float* bq = (const float*)d_in[4];
    const float* Wk = (const float*)d_in[5];
    const float* bk = (const float*)d_in[6];
    const float* Wv = (const float*)d_in[7];
    const float* bv = (const float*)d_in[8];
    const float* Wo = (const float*)d_in[9];
    const float* bo = (const float*)d_in[10];
    float* out = (float*)d_out;

    cudaFuncSetAttribute(mega, cudaFuncAttributeMaxDynamicSharedMemorySize, GSMEM_TOTAL);

    __half *qkv, *xh, *wth, *yh;
    cudaGetSymbolAddress((void**)&qkv, g_qkv);
    cudaGetSymbolAddress((void**)&xh, g_xh);
    cudaGetSymbolAddress((void**)&wth, g_wth);
    cudaGetSymbolAddress((void**)&yh, g_yh);

    // 1) preprocessing + flag reset
    preprocess<<<1024 + 3 * (ND / 1024), 256>>>(Wq, Wk, Wv, Wo, x_q, x_k, x_v, wth, xh);

    // 2) megakernel: QKV GEMM -> attention -> O GEMM with dataflow overlap
    MegaArgs a;
    a.xh = xh;
    a.wth = wth;
    a.bias[0] = bq; a.bias[1] = bk; a.bias[2] = bv; a.bias[3] = bo;
    a.qkv = qkv;
    a.xq = x_q;
    a.yh = yh;
    a.out = out;
    mega<<<768 + 1024 + 256, 256, GSMEM_TOTAL>>>(a);
}